// round 1
// baseline (speedup 1.0000x reference)
#include <cuda_runtime.h>
#include <math.h>

#define EMBD   300
#define UNITS  512
#define BATCH  64
#define TLEN   512
#define NC     3072   // 2 * 3 * UNITS

// ---------------- scratch (device globals; no allocations allowed) ----------
__device__ float g_xw[(size_t)TLEN * NC * BATCH];   // [t][c][b]  c in [0,3072)
__device__ float g_h[2 * 2 * UNITS * BATCH];        // [dir][parity][k][b]
__device__ unsigned int g_bar_count;
__device__ unsigned int g_bar_gen;

// ---------------- Kernel 1: embedding gather + input GEMM -------------------
// C[(t,b)][c] = emb[tokens[b][t]] @ W(dir) + bias_row0 ; stored g_xw[t][c][b]
__global__ __launch_bounds__(256) void embed_gemm(
    const int* __restrict__ tokens, const float* __restrict__ emb,
    const float* __restrict__ Wf, const float* __restrict__ Wb,
    const float* __restrict__ bf, const float* __restrict__ bb)
{
    __shared__ float As[16][64];   // [kk][row(b)]
    __shared__ float Bs[16][64];   // [kk][col]
    __shared__ float Cs[64][65];   // [c_local][b]

    const int t   = blockIdx.y;          // one row-block == one timestep (64 b rows)
    const int c0  = blockIdx.x * 64;     // global column base (0..3071)
    const int tid = threadIdx.x;
    const int tx  = tid & 15;            // col group
    const int ty  = tid >> 4;            // row group

    // A loader mapping: row = tid>>2 (batch), 4 contiguous k per thread
    const int arow = tid >> 2;
    const int akk  = (tid & 3) * 4;
    const int tok  = tokens[(size_t)arow * TLEN + t];
    const float* aptr = emb + (size_t)tok * EMBD;

    // B loader mapping
    const int bkk  = tid >> 4;
    const int bcol = (tid & 15) * 4;
    const bool fwd = (c0 < 1536);
    const float* W   = fwd ? Wf : Wb;
    const int    wc0 = fwd ? c0 : (c0 - 1536);

    float acc[4][4];
    #pragma unroll
    for (int i = 0; i < 4; i++)
        #pragma unroll
        for (int j = 0; j < 4; j++) acc[i][j] = 0.f;

    for (int k0 = 0; k0 < EMBD; k0 += 16) {
        #pragma unroll
        for (int i = 0; i < 4; i++) {
            int k = k0 + akk + i;
            As[akk + i][arow] = (k < EMBD) ? aptr[k] : 0.f;
        }
        {
            int k = k0 + bkk;
            if (k < EMBD) {
                const float* wp = W + (size_t)k * 1536 + wc0 + bcol;
                #pragma unroll
                for (int j = 0; j < 4; j++) Bs[bkk][bcol + j] = wp[j];
            } else {
                #pragma unroll
                for (int j = 0; j < 4; j++) Bs[bkk][bcol + j] = 0.f;
            }
        }
        __syncthreads();
        #pragma unroll
        for (int kk = 0; kk < 16; kk++) {
            const float4 a4 = *(const float4*)&As[kk][ty * 4];
            const float4 b4 = *(const float4*)&Bs[kk][tx * 4];
            const float av[4] = {a4.x, a4.y, a4.z, a4.w};
            const float bv[4] = {b4.x, b4.y, b4.z, b4.w};
            #pragma unroll
            for (int i = 0; i < 4; i++)
                #pragma unroll
                for (int j = 0; j < 4; j++)
                    acc[i][j] += av[i] * bv[j];
        }
        __syncthreads();
    }

    // bias (row 0 of (2,1536)) + transpose into Cs[c][b]
    const float* bias = fwd ? bf : bb;
    #pragma unroll
    for (int j = 0; j < 4; j++) {
        float bv = bias[wc0 + tx * 4 + j];
        #pragma unroll
        for (int i = 0; i < 4; i++)
            Cs[tx * 4 + j][ty * 4 + i] = acc[i][j] + bv;
    }
    __syncthreads();

    // coalesced store: g_xw[t][c0+cl][b]
    {
        const int cl  = tid >> 2;          // 0..63
        const int bb0 = (tid & 3) * 16;    // 16 consecutive b
        float* dst = g_xw + ((size_t)t * NC + c0 + cl) * BATCH + bb0;
        #pragma unroll
        for (int j = 0; j < 16; j += 4) {
            float4 v = make_float4(Cs[cl][bb0 + j], Cs[cl][bb0 + j + 1],
                                   Cs[cl][bb0 + j + 2], Cs[cl][bb0 + j + 3]);
            *(float4*)(dst + j) = v;
        }
    }
}

// ---------------- grid barrier (all blocks resident: grid=128 <= 148 SMs) ---
__device__ __forceinline__ void gridbar(int nblk)
{
    __syncthreads();
    if (threadIdx.x == 0) {
        __threadfence();
        unsigned int gen0 = atomicAdd(&g_bar_gen, 0u);
        unsigned int my   = atomicAdd(&g_bar_count, 1u);
        if (my == (unsigned)nblk - 1u) {
            atomicExch(&g_bar_count, 0u);
            __threadfence();
            atomicAdd(&g_bar_gen, 1u);
        } else {
            while (atomicAdd(&g_bar_gen, 0u) == gen0) __nanosleep(64);
        }
        __threadfence();
    }
    __syncthreads();
}

// ---------------- Kernel 2: persistent bidirectional GRU scan ---------------
// grid = 128 blocks: blockIdx.x&1 = direction, >>1 = 8-unit column slab (0..63)
// smem: Us[512][24] (U slab, resident whole scan) | hs[512][64] ([k][b]) |
//       part[4][1536] (k-split partials)
__global__ __launch_bounds__(256, 1) void gru_scan(
    const float* __restrict__ Uf, const float* __restrict__ Ub,
    const float* __restrict__ bf, const float* __restrict__ bb,
    float* __restrict__ out)
{
    extern __shared__ float sm[];
    float* Us   = sm;                    // 512*24
    float* hs   = Us + 512 * 24;         // 512*64
    float* part = hs + 512 * 64;         // 4*1536
    __shared__ float brec[24];

    const int dir = blockIdx.x & 1;
    const int cb  = blockIdx.x >> 1;     // 0..63
    const int u0  = cb * 8;
    const int tid = threadIdx.x;

    const float* U    = dir ? Ub : Uf;
    const float* brow = (dir ? bb : bf) + 1536;   // recurrent bias (row 1)

    // load U slab: Us[k][g*8+ui] = U[k][g*512 + u0 + ui]
    for (int l = tid; l < 512 * 24; l += 256) {
        int k = l / 24, j = l % 24;
        int g = j >> 3, ui = j & 7;
        Us[l] = U[(size_t)k * 1536 + g * 512 + u0 + ui];
    }
    if (tid < 24) {
        int g = tid >> 3, ui = tid & 7;
        brec[tid] = brow[g * 512 + u0 + ui];
    }
    // zero h ping-pong buffers cooperatively
    for (int l = blockIdx.x * 256 + tid; l < 2 * 2 * UNITS * BATCH; l += 128 * 256)
        g_h[l] = 0.f;
    gridbar(128);

    // thread tiling for the matvec: 4 batch x 2 units x 3 gates, k split 4-way
    const int ug = tid & 3;              // unit pair (local units ug*2, ug*2+1)
    const int bg = (tid >> 2) & 15;      // batch group
    const int kh = tid >> 6;             // k quarter (0..3)
    const int b0 = bg * 4;
    const int uA = ug * 2;

    for (int s = 0; s < TLEN; s++) {
        const int p = s & 1;
        const int t = dir ? (TLEN - 1 - s) : s;   // xw index == output time index

        // stage h_old into smem, [k][b] layout (coalesced float4)
        const float* hg = g_h + ((size_t)(dir * 2 + p) * UNITS) * BATCH;
        for (int l = tid * 4; l < UNITS * BATCH; l += 256 * 4)
            *(float4*)(hs + l) = *(const float4*)(hg + l);
        __syncthreads();

        // rec partials over this thread's k quarter
        float acc[2][3][4];
        #pragma unroll
        for (int uu = 0; uu < 2; uu++)
            #pragma unroll
            for (int g = 0; g < 3; g++)
                #pragma unroll
                for (int bi = 0; bi < 4; bi++) acc[uu][g][bi] = 0.f;

        const float* hp = hs + (size_t)kh * 128 * 64 + b0;
        const float* up = Us + (size_t)kh * 128 * 24 + uA;
        #pragma unroll 2
        for (int k = 0; k < 128; k++) {
            const float4 h4 = *(const float4*)(hp + k * 64);
            const float2 uz = *(const float2*)(up + k * 24);
            const float2 ur = *(const float2*)(up + k * 24 + 8);
            const float2 uh = *(const float2*)(up + k * 24 + 16);
            const float hv[4]    = {h4.x, h4.y, h4.z, h4.w};
            const float uv[2][3] = {{uz.x, ur.x, uh.x}, {uz.y, ur.y, uh.y}};
            #pragma unroll
            for (int uu = 0; uu < 2; uu++)
                #pragma unroll
                for (int g = 0; g < 3; g++)
                    #pragma unroll
                    for (int bi = 0; bi < 4; bi++)
                        acc[uu][g][bi] += uv[uu][g] * hv[bi];
        }

        // write partials (separate scratch; hs stays intact for h_old reads)
        #pragma unroll
        for (int uu = 0; uu < 2; uu++)
            #pragma unroll
            for (int g = 0; g < 3; g++)
                #pragma unroll
                for (int bi = 0; bi < 4; bi++)
                    part[kh * 1536 + (g * 8 + uA + uu) * 64 + b0 + bi] = acc[uu][g][bi];
        __syncthreads();

        // combine: 512 h_new values (8 units x 64 batch), 2 per thread
        float* hw = g_h + ((size_t)(dir * 2 + (p ^ 1)) * UNITS) * BATCH;
        #pragma unroll
        for (int e = 0; e < 2; e++) {
            const int n = tid * 2 + e;
            const int u = n >> 6;        // local unit 0..7
            const int b = n & 63;
            float rz = brec[u], rr = brec[8 + u], rh = brec[16 + u];
            #pragma unroll
            for (int q = 0; q < 4; q++) {
                rz += part[q * 1536 + (u)      * 64 + b];
                rr += part[q * 1536 + (8 + u)  * 64 + b];
                rh += part[q * 1536 + (16 + u) * 64 + b];
            }
            const size_t xwbase = ((size_t)t * NC + dir * 1536) * BATCH;
            const float xz = g_xw[xwbase + (size_t)(u0 + u) * BATCH + b];
            const float xr = g_xw[xwbase + (size_t)(512 + u0 + u) * BATCH + b];
            const float xh = g_xw[xwbase + (size_t)(1024 + u0 + u) * BATCH + b];
            const float hold = hs[(u0 + u) * 64 + b];

            const float z  = 1.f / (1.f + expf(-(xz + rz)));
            const float r  = 1.f / (1.f + expf(-(xr + rr)));
            const float hh = tanhf(xh + r * rh);
            const float hn = z * hold + (1.f - z) * hh;

            hw[(u0 + u) * BATCH + b] = hn;
            out[((size_t)b * TLEN + t) * 1024 + dir * 512 + u0 + u] = hn;
            if (s == TLEN - 1)
                out[(size_t)BATCH * TLEN * 1024 + (size_t)b * 1024 + dir * 512 + u0 + u] = hn;
        }
        gridbar(128);
    }
}

// ---------------- launch ----------------------------------------------------
extern "C" void kernel_launch(void* const* d_in, const int* in_sizes, int n_in,
                              void* d_out, int out_size)
{
    const int*   tokens = (const int*)  d_in[0];
    const float* emb    = (const float*)d_in[1];
    const float* W_f    = (const float*)d_in[2];
    const float* U_f    = (const float*)d_in[3];
    const float* b_f    = (const float*)d_in[4];
    const float* W_b    = (const float*)d_in[5];
    const float* U_b    = (const float*)d_in[6];
    const float* b_b    = (const float*)d_in[7];
    float* out = (float*)d_out;

    (void)in_sizes; (void)n_in; (void)out_size;

    // Kernel 1: input projection for both directions
    dim3 g1(NC / 64, TLEN);
    embed_gemm<<<g1, 256>>>(tokens, emb, W_f, W_b, b_f, b_b);

    // Kernel 2: persistent scan (128 blocks, ~200KB dynamic smem each)
    const size_t smem = (512 * 24 + 512 * 64 + 4 * 1536) * sizeof(float); // 204800
    cudaFuncSetAttribute(gru_scan, cudaFuncAttributeMaxDynamicSharedMemorySize,
                         (int)smem);
    gru_scan<<<128, 256, smem>>>(U_f, U_b, b_f, b_b, out);
}

// round 2
// speedup vs baseline: 1.0483x; 1.0483x over previous
#include <cuda_runtime.h>
#include <math.h>

typedef unsigned long long ull;

#define EMBD   300
#define UNITS  512
#define BATCH  64
#define TLEN   512
#define NC     3072   // 2 * 3 * UNITS

// ---------------- scratch (device globals; no allocations allowed) ----------
__device__ float g_xw[(size_t)TLEN * NC * BATCH];   // [t][c][b]
__device__ float g_h[2 * 2 * UNITS * BATCH];        // [dir][parity][k][b]
__device__ unsigned int g_bar_count;
__device__ unsigned int g_bar_gen;

// ---------------- packed fp32x2 helpers (sm_103a dual fp32 pipe) ------------
__device__ __forceinline__ ull pk2(float lo, float hi) {
    ull r; asm("mov.b64 %0, {%1, %2};" : "=l"(r) : "f"(lo), "f"(hi)); return r;
}
__device__ __forceinline__ void fma2(ull& d, ull a, ull b) {
    asm("fma.rn.f32x2 %0, %1, %2, %0;" : "+l"(d) : "l"(a), "l"(b));
}
__device__ __forceinline__ float2 upk2(ull v) {
    float2 r; asm("mov.b64 {%0, %1}, %2;" : "=f"(r.x), "=f"(r.y) : "l"(v)); return r;
}

// ---------------- Kernel 1: embedding gather + input GEMM -------------------
// C[(t,b)][c] = emb[tokens[b][t]] @ W(dir) + bias_row0 ; stored g_xw[t][c][b]
__global__ __launch_bounds__(256) void embed_gemm(
    const int* __restrict__ tokens, const float* __restrict__ emb,
    const float* __restrict__ Wf, const float* __restrict__ Wb,
    const float* __restrict__ bf, const float* __restrict__ bb)
{
    __shared__ float As[16][64];   // [kk][row(b)]
    __shared__ float Bs[16][64];   // [kk][col]
    __shared__ float Cs[64][65];   // [c_local][b]

    const int t   = blockIdx.y;
    const int c0  = blockIdx.x * 64;
    const int tid = threadIdx.x;
    const int tx  = tid & 15;
    const int ty  = tid >> 4;

    const int arow = tid >> 2;
    const int akk  = (tid & 3) * 4;
    const int tok  = tokens[(size_t)arow * TLEN + t];
    const float* aptr = emb + (size_t)tok * EMBD;

    const int bkk  = tid >> 4;
    const int bcol = (tid & 15) * 4;
    const bool fwd = (c0 < 1536);
    const float* W   = fwd ? Wf : Wb;
    const int    wc0 = fwd ? c0 : (c0 - 1536);

    ull acc2[4][2];
    #pragma unroll
    for (int i = 0; i < 4; i++) { acc2[i][0] = 0ull; acc2[i][1] = 0ull; }

    for (int k0 = 0; k0 < EMBD; k0 += 16) {
        #pragma unroll
        for (int i = 0; i < 4; i++) {
            int k = k0 + akk + i;
            As[akk + i][arow] = (k < EMBD) ? aptr[k] : 0.f;
        }
        {
            int k = k0 + bkk;
            if (k < EMBD) {
                const float* wp = W + (size_t)k * 1536 + wc0 + bcol;
                #pragma unroll
                for (int j = 0; j < 4; j++) Bs[bkk][bcol + j] = wp[j];
            } else {
                #pragma unroll
                for (int j = 0; j < 4; j++) Bs[bkk][bcol + j] = 0.f;
            }
        }
        __syncthreads();
        #pragma unroll
        for (int kk = 0; kk < 16; kk++) {
            const float4 a4 = *(const float4*)&As[kk][ty * 4];
            const ull*   b64 = (const ull*)&Bs[kk][tx * 4];
            const ull bp0 = b64[0], bp1 = b64[1];
            ull ad;
            ad = pk2(a4.x, a4.x); fma2(acc2[0][0], ad, bp0); fma2(acc2[0][1], ad, bp1);
            ad = pk2(a4.y, a4.y); fma2(acc2[1][0], ad, bp0); fma2(acc2[1][1], ad, bp1);
            ad = pk2(a4.z, a4.z); fma2(acc2[2][0], ad, bp0); fma2(acc2[2][1], ad, bp1);
            ad = pk2(a4.w, a4.w); fma2(acc2[3][0], ad, bp0); fma2(acc2[3][1], ad, bp1);
        }
        __syncthreads();
    }

    const float* bias = fwd ? bf : bb;
    float bv[4];
    #pragma unroll
    for (int j = 0; j < 4; j++) bv[j] = bias[wc0 + tx * 4 + j];
    #pragma unroll
    for (int i = 0; i < 4; i++) {
        float2 c0v = upk2(acc2[i][0]);
        float2 c1v = upk2(acc2[i][1]);
        Cs[tx * 4 + 0][ty * 4 + i] = c0v.x + bv[0];
        Cs[tx * 4 + 1][ty * 4 + i] = c0v.y + bv[1];
        Cs[tx * 4 + 2][ty * 4 + i] = c1v.x + bv[2];
        Cs[tx * 4 + 3][ty * 4 + i] = c1v.y + bv[3];
    }
    __syncthreads();

    {
        const int cl  = tid >> 2;
        const int bb0 = (tid & 3) * 16;
        float* dst = g_xw + ((size_t)t * NC + c0 + cl) * BATCH + bb0;
        #pragma unroll
        for (int j = 0; j < 16; j += 4) {
            float4 v = make_float4(Cs[cl][bb0 + j], Cs[cl][bb0 + j + 1],
                                   Cs[cl][bb0 + j + 2], Cs[cl][bb0 + j + 3]);
            *(float4*)(dst + j) = v;
        }
    }
}

// ---------------- grid barrier (128 blocks, all resident) -------------------
__device__ __forceinline__ void gridbar(int nblk)
{
    __threadfence();            // every thread publishes its h stores
    __syncthreads();
    if (threadIdx.x == 0) {
        unsigned int gen0 = *(volatile unsigned int*)&g_bar_gen;
        unsigned int my   = atomicAdd(&g_bar_count, 1u);
        if (my == (unsigned)nblk - 1u) {
            atomicExch(&g_bar_count, 0u);
            __threadfence();
            atomicAdd(&g_bar_gen, 1u);
        } else {
            while (*(volatile unsigned int*)&g_bar_gen == gen0) __nanosleep(32);
        }
    }
    __syncthreads();
}

// ---------------- Kernel 2: persistent bidirectional GRU scan ---------------
// grid = 128: blockIdx&1 = dir, >>1 = 8-unit slab. 512 threads/block.
// smem: Us[512][24] | hs[512][64] | part[4][24*65 padded]
__global__ __launch_bounds__(512, 1) void gru_scan(
    const float* __restrict__ Uf, const float* __restrict__ Ub,
    const float* __restrict__ bf, const float* __restrict__ bb,
    float* __restrict__ out)
{
    extern __shared__ float sm[];
    float* Us   = sm;                    // 512*24 = 12288
    float* hs   = Us + 512 * 24;         // 512*64 = 32768
    float* part = hs + 512 * 64;         // 4*1560 = 6240 (row stride 65)
    __shared__ float brec[24];

    const int dir = blockIdx.x & 1;
    const int cb  = blockIdx.x >> 1;
    const int u0  = cb * 8;
    const int tid = threadIdx.x;

    const float* U    = dir ? Ub : Uf;
    const float* brow = (dir ? bb : bf) + 1536;

    // U slab: Us[k][g*8+ui] = U[k][g*512 + u0 + ui]
    for (int l = tid; l < 512 * 24; l += 512) {
        int k = l / 24, j = l % 24;
        int g = j >> 3, ui = j & 7;
        Us[l] = U[(size_t)k * 1536 + g * 512 + u0 + ui];
    }
    if (tid < 24) {
        int g = tid >> 3, ui = tid & 7;
        brec[tid] = brow[g * 512 + u0 + ui];
    }
    for (int l = blockIdx.x * 512 + tid; l < 2 * 2 * UNITS * BATCH; l += 128 * 512)
        g_h[l] = 0.f;
    gridbar(128);

    // matvec tiling: kh = k-quarter, within quarter: 4 unit-pairs x 32 batch-pairs
    const int kh = tid >> 7;             // 0..3
    const int r  = tid & 127;
    const int ug = r & 3;                // unit pair -> local units 2ug, 2ug+1
    const int bg = r >> 2;               // 0..31 -> batches 2bg, 2bg+1

    // combine mapping: one h_new per thread, units contiguous per warp
    const int cu = tid & 7;              // local unit
    const int cbt = tid >> 3;            // batch 0..63

    for (int s = 0; s < TLEN; s++) {
        const int p = s & 1;
        const int t = dir ? (TLEN - 1 - s) : s;

        // stage h_old ([k][b], float4 coalesced)
        {
            const float4* hg4 = (const float4*)(g_h + (size_t)(dir * 2 + p) * UNITS * BATCH);
            float4* hs4 = (float4*)hs;
            #pragma unroll
            for (int l = tid; l < UNITS * BATCH / 4; l += 512) hs4[l] = hg4[l];
        }
        __syncthreads();

        // rec partials over this thread's k quarter — packed f32x2 over unit pair
        ull az0 = 0, az1 = 0, ar0 = 0, ar1 = 0, ah0 = 0, ah1 = 0;
        {
            const float2* hp2  = (const float2*)(hs + (size_t)kh * 128 * 64) + bg;
            const ull*    up64 = (const ull*)(Us + (size_t)kh * 128 * 24) + ug;
            #pragma unroll 4
            for (int k = 0; k < 128; k++) {
                const float2 h2 = hp2[k * 32];
                const ull hd0 = pk2(h2.x, h2.x);
                const ull hd1 = pk2(h2.y, h2.y);
                const ull uz = up64[k * 12];
                const ull ur = up64[k * 12 + 4];
                const ull uh = up64[k * 12 + 8];
                fma2(az0, uz, hd0); fma2(az1, uz, hd1);
                fma2(ar0, ur, hd0); fma2(ar1, ur, hd1);
                fma2(ah0, uh, hd0); fma2(ah1, uh, hd1);
            }
        }
        {
            float* pp = part + kh * 1560;
            const int uA = ug * 2, b = bg * 2;
            float2 v;
            v = upk2(az0); pp[(uA) * 65 + b]     = v.x; pp[(uA + 1) * 65 + b]     = v.y;
            v = upk2(az1); pp[(uA) * 65 + b + 1] = v.x; pp[(uA + 1) * 65 + b + 1] = v.y;
            v = upk2(ar0); pp[(8 + uA) * 65 + b]     = v.x; pp[(9 + uA) * 65 + b]     = v.y;
            v = upk2(ar1); pp[(8 + uA) * 65 + b + 1] = v.x; pp[(9 + uA) * 65 + b + 1] = v.y;
            v = upk2(ah0); pp[(16 + uA) * 65 + b]     = v.x; pp[(17 + uA) * 65 + b]     = v.y;
            v = upk2(ah1); pp[(16 + uA) * 65 + b + 1] = v.x; pp[(17 + uA) * 65 + b + 1] = v.y;
        }
        __syncthreads();

        // combine: 512 h_new (8 units x 64 batch), one per thread
        {
            const int u = cu, b = cbt;
            float rz = brec[u], rr = brec[8 + u], rh = brec[16 + u];
            #pragma unroll
            for (int q = 0; q < 4; q++) {
                rz += part[q * 1560 + (u) * 65 + b];
                rr += part[q * 1560 + (8 + u) * 65 + b];
                rh += part[q * 1560 + (16 + u) * 65 + b];
            }
            const float* xwp = g_xw + ((size_t)t * NC + dir * 1536) * BATCH;
            const float xz = xwp[(size_t)(u0 + u) * BATCH + b];
            const float xr = xwp[(size_t)(512 + u0 + u) * BATCH + b];
            const float xh = xwp[(size_t)(1024 + u0 + u) * BATCH + b];
            const float hold = hs[(u0 + u) * 64 + b];

            const float z  = 1.f / (1.f + expf(-(xz + rz)));
            const float rg = 1.f / (1.f + expf(-(xr + rr)));
            const float hh = tanhf(xh + rg * rh);
            const float hn = z * hold + (1.f - z) * hh;

            float* hw = g_h + (size_t)(dir * 2 + (p ^ 1)) * UNITS * BATCH;
            hw[(u0 + u) * BATCH + b] = hn;
            out[((size_t)b * TLEN + t) * 1024 + dir * 512 + u0 + u] = hn;
            if (s == TLEN - 1)
                out[(size_t)BATCH * TLEN * 1024 + (size_t)b * 1024 + dir * 512 + u0 + u] = hn;
        }
        gridbar(128);
    }
}

// ---------------- launch ----------------------------------------------------
extern "C" void kernel_launch(void* const* d_in, const int* in_sizes, int n_in,
                              void* d_out, int out_size)
{
    const int*   tokens = (const int*)  d_in[0];
    const float* emb    = (const float*)d_in[1];
    const float* W_f    = (const float*)d_in[2];
    const float* U_f    = (const float*)d_in[3];
    const float* b_f    = (const float*)d_in[4];
    const float* W_b    = (const float*)d_in[5];
    const float* U_b    = (const float*)d_in[6];
    const float* b_b    = (const float*)d_in[7];
    float* out = (float*)d_out;

    (void)in_sizes; (void)n_in; (void)out_size;

    dim3 g1(NC / 64, TLEN);
    embed_gemm<<<g1, 256>>>(tokens, emb, W_f, W_b, b_f, b_b);

    const size_t smem = (512 * 24 + 512 * 64 + 4 * 1560) * sizeof(float); // 205184
    cudaFuncSetAttribute(gru_scan, cudaFuncAttributeMaxDynamicSharedMemorySize,
                         (int)smem);
    gru_scan<<<128, 512, smem>>>(U_f, U_b, b_f, b_b, out);
}

// round 5
// speedup vs baseline: 1.0602x; 1.0113x over previous
#include <cuda_runtime.h>
#include <math.h>

typedef unsigned long long ull;

#define EMBD   300
#define UNITS  512
#define BATCH  64
#define TLEN   512
#define NC     3072   // 2 * 3 * UNITS

// scan decomposition: 128 blocks = 2 dir x 2 batch-halves x 32 unit-slabs
#define UPB    16     // units per block
#define BPG    32     // batches per group

// ---------------- scratch (device globals; no allocations allowed) ----------
__device__ float g_xw[(size_t)TLEN * NC * BATCH];          // [t][c][b]
__device__ float g_h[2 * 2 * 2 * UNITS * BPG];             // [dir][bgrp][par][k][b32]
__device__ unsigned int g_cnt[4];
__device__ unsigned int g_gen[4];

// ---------------- packed fp32x2 helpers -------------------------------------
__device__ __forceinline__ ull pk2(float lo, float hi) {
    ull r; asm("mov.b64 %0, {%1, %2};" : "=l"(r) : "f"(lo), "f"(hi)); return r;
}
__device__ __forceinline__ void fma2(ull& d, ull a, ull b) {
    asm("fma.rn.f32x2 %0, %1, %2, %0;" : "+l"(d) : "l"(a), "l"(b));
}
__device__ __forceinline__ float2 upk2(ull v) {
    float2 r; asm("mov.b64 {%0, %1}, %2;" : "=f"(r.x), "=f"(r.y) : "l"(v)); return r;
}

// ---------------- Kernel 1: embedding gather + input GEMM (64b x 128c) ------
__global__ __launch_bounds__(256) void embed_gemm(
    const int* __restrict__ tokens, const float* __restrict__ emb,
    const float* __restrict__ Wf, const float* __restrict__ Wb,
    const float* __restrict__ bf, const float* __restrict__ bb)
{
    __shared__ float As[16][64];    // [kk][b]
    __shared__ float Bs[16][128];   // [kk][c]
    __shared__ float Cs[128][65];   // [c][b]

    const int t   = blockIdx.y;
    const int c0  = blockIdx.x * 128;          // 0..2944, 1536-boundary aligned
    const int tid = threadIdx.x;
    const int tx  = tid & 15;                  // c-group (8 cols)
    const int ty  = tid >> 4;                  // b-group (4 rows)

    // A loader: row = tid>>2, 4 k per thread
    const int arow = tid >> 2;
    const int akk  = (tid & 3) * 4;
    const int tok  = tokens[(size_t)arow * TLEN + t];
    const float* aptr = emb + (size_t)tok * EMBD;

    // B loader: row = tid>>4 (0..15), 8 cols
    const int brow = tid >> 4;
    const int bcol = (tid & 15) * 8;
    const bool fwd = (c0 < 1536);
    const float* W   = fwd ? Wf : Wb;
    const int    wc0 = fwd ? c0 : (c0 - 1536);

    ull acc2[4][4];
    #pragma unroll
    for (int i = 0; i < 4; i++)
        #pragma unroll
        for (int j = 0; j < 4; j++) acc2[i][j] = 0ull;

    for (int k0 = 0; k0 < EMBD; k0 += 16) {
        #pragma unroll
        for (int i = 0; i < 4; i++) {
            int k = k0 + akk + i;
            As[akk + i][arow] = (k < EMBD) ? aptr[k] : 0.f;
        }
        {
            int k = k0 + brow;
            if (k < EMBD) {
                const float* wp = W + (size_t)k * 1536 + wc0 + bcol;
                *(float4*)&Bs[brow][bcol]     = *(const float4*)wp;
                *(float4*)&Bs[brow][bcol + 4] = *(const float4*)(wp + 4);
            } else {
                *(float4*)&Bs[brow][bcol]     = make_float4(0, 0, 0, 0);
                *(float4*)&Bs[brow][bcol + 4] = make_float4(0, 0, 0, 0);
            }
        }
        __syncthreads();
        #pragma unroll
        for (int kk = 0; kk < 16; kk++) {
            const float4 a4 = *(const float4*)&As[kk][ty * 4];
            const float4 b0 = *(const float4*)&Bs[kk][tx * 8];
            const float4 b1 = *(const float4*)&Bs[kk][tx * 8 + 4];
            const ull bp[4] = {pk2(b0.x, b0.y), pk2(b0.z, b0.w),
                               pk2(b1.x, b1.y), pk2(b1.z, b1.w)};
            const float av[4] = {a4.x, a4.y, a4.z, a4.w};
            #pragma unroll
            for (int i = 0; i < 4; i++) {
                const ull ad = pk2(av[i], av[i]);
                #pragma unroll
                for (int j = 0; j < 4; j++) fma2(acc2[i][j], ad, bp[j]);
            }
        }
        __syncthreads();
    }

    const float* bias = fwd ? bf : bb;
    #pragma unroll
    for (int j = 0; j < 4; j++) {
        const float2 bv = make_float2(bias[wc0 + tx * 8 + j * 2],
                                      bias[wc0 + tx * 8 + j * 2 + 1]);
        #pragma unroll
        for (int i = 0; i < 4; i++) {
            const float2 v = upk2(acc2[i][j]);
            Cs[tx * 8 + j * 2][ty * 4 + i]     = v.x + bv.x;
            Cs[tx * 8 + j * 2 + 1][ty * 4 + i] = v.y + bv.y;
        }
    }
    __syncthreads();

    {   // coalesced store: g_xw[t][c0+cl][b]
        const int cl  = tid >> 1;              // 0..127
        const int bb0 = (tid & 1) * 32;
        float* dst = g_xw + ((size_t)t * NC + c0 + cl) * BATCH + bb0;
        #pragma unroll
        for (int j = 0; j < 32; j += 4) {
            float4 v = make_float4(Cs[cl][bb0 + j], Cs[cl][bb0 + j + 1],
                                   Cs[cl][bb0 + j + 2], Cs[cl][bb0 + j + 3]);
            *(float4*)(dst + j) = v;
        }
    }
}

// ---------------- per-group grid barrier (32 blocks, release/acquire) -------
__device__ __forceinline__ void gridbar_group(int gid, int nblk)
{
    __syncthreads();
    if (threadIdx.x == 0) {
        __threadfence();   // release: block's stores (cumulative via syncthreads)
        unsigned int gen0 = *(volatile unsigned int*)&g_gen[gid];
        unsigned int my   = atomicAdd(&g_cnt[gid], 1u);
        if (my == (unsigned)nblk - 1u) {
            *(volatile unsigned int*)&g_cnt[gid] = 0u;
            __threadfence();
            atomicAdd(&g_gen[gid], 1u);
        } else {
            while (*(volatile unsigned int*)&g_gen[gid] == gen0) __nanosleep(20);
        }
        __threadfence();   // acquire
    }
    __syncthreads();
}

// ---------------- Kernel 2: persistent bidirectional GRU scan ---------------
// block = (dir, bgrp, unit-slab of 16). smem: Us[512][48] | hs[512][32] | part
__global__ __launch_bounds__(256, 1) void gru_scan(
    const float* __restrict__ Uf, const float* __restrict__ Ub,
    const float* __restrict__ bf, const float* __restrict__ bb,
    float* __restrict__ out)
{
    extern __shared__ float sm[];
    float* Us   = sm;                    // 512*48 = 24576
    float* hs   = Us + 512 * 48;         // 512*32 = 16384
    float* part = hs + 512 * 32;         // 12 * 576 = 6912 (row pad 18)
    __shared__ float brec[48];

    const int tid  = threadIdx.x;
    const int bid  = blockIdx.x;
    const int dir  = bid >> 6;
    const int bgrp = (bid >> 5) & 1;
    const int us   = bid & 31;
    const int gid  = dir * 2 + bgrp;
    const int u0   = us * UPB;
    const int B0   = bgrp * BPG;

    const float* U    = dir ? Ub : Uf;
    const float* brow = (dir ? bb : bf) + 1536;

    // U slab: Us[k][g*16+ui] = U[k][g*512 + u0 + ui]
    for (int l = tid; l < 512 * 48; l += 256) {
        int k = l / 48, j = l % 48;
        int g = j >> 4, ui = j & 15;
        Us[l] = U[(size_t)k * 1536 + g * 512 + u0 + ui];
    }
    if (tid < 48) brec[tid] = brow[(tid >> 4) * 512 + u0 + (tid & 15)];

    // zero this group's h ping-pong (32 blocks x 256 thr x 4 floats = 32768)
    {
        float* hz = g_h + (size_t)gid * 2 * UNITS * BPG;
        int l = (us * 256 + tid) * 4;
        *(float4*)(hz + l) = make_float4(0, 0, 0, 0);
    }
    gridbar_group(gid, 32);

    // matvec tiling: kh = k-quarter; uh = 4-unit group; bg = 2-batch group
    const int kh = tid >> 6;
    const int uh = tid & 3;
    const int bg = (tid >> 2) & 15;

    // combine mapping: cb = batch lane, cu2 = unit pair
    const int cb  = tid & 31;
    const int cu2 = tid >> 5;            // 0..7 -> units cu2*2, cu2*2+1

    for (int s = 0; s < TLEN; s++) {
        const int p = s & 1;
        const int t = dir ? (TLEN - 1 - s) : s;

        // prefetch xw for combine (DRAM latency hidden under matvec)
        float xg[6];
        {
            const float* xp = g_xw + ((size_t)t * NC + dir * 1536 + u0 + cu2 * 2) * BATCH
                              + B0 + cb;
            #pragma unroll
            for (int g = 0; g < 3; g++) {
                xg[g * 2]     = __ldg(xp + (size_t)g * 512 * BATCH);
                xg[g * 2 + 1] = __ldg(xp + ((size_t)g * 512 + 1) * BATCH);
            }
        }

        // stage h_old slice [k][b32]
        {
            const float4* hg4 = (const float4*)(g_h +
                ((size_t)gid * 2 + p) * UNITS * BPG);
            float4* hs4 = (float4*)hs;
            #pragma unroll
            for (int l = tid; l < UNITS * BPG / 4; l += 256) hs4[l] = hg4[l];
        }
        __syncthreads();

        // rec partials: 4 units (2 ull) x 2 batches x 3 gates over k quarter
        ull az[2][2], ar[2][2], ah[2][2];
        #pragma unroll
        for (int i = 0; i < 2; i++)
            #pragma unroll
            for (int j = 0; j < 2; j++) { az[i][j] = ar[i][j] = ah[i][j] = 0ull; }
        {
            const float* hp = hs + (size_t)kh * 128 * 32 + bg * 2;
            const float* up = Us + (size_t)kh * 128 * 48 + uh * 4;
            #pragma unroll 2
            for (int k = 0; k < 128; k++) {
                const float2 h2 = *(const float2*)(hp + k * 32);
                const ull hd0 = pk2(h2.x, h2.x);
                const ull hd1 = pk2(h2.y, h2.y);
                const float4 z4 = *(const float4*)(up + k * 48);
                const float4 r4 = *(const float4*)(up + k * 48 + 16);
                const float4 q4 = *(const float4*)(up + k * 48 + 32);
                const ull z0 = pk2(z4.x, z4.y), z1 = pk2(z4.z, z4.w);
                const ull r0 = pk2(r4.x, r4.y), r1 = pk2(r4.z, r4.w);
                const ull q0 = pk2(q4.x, q4.y), q1 = pk2(q4.z, q4.w);
                fma2(az[0][0], z0, hd0); fma2(az[1][0], z1, hd0);
                fma2(az[0][1], z0, hd1); fma2(az[1][1], z1, hd1);
                fma2(ar[0][0], r0, hd0); fma2(ar[1][0], r1, hd0);
                fma2(ar[0][1], r0, hd1); fma2(ar[1][1], r1, hd1);
                fma2(ah[0][0], q0, hd0); fma2(ah[1][0], q1, hd0);
                fma2(ah[0][1], q0, hd1); fma2(ah[1][1], q1, hd1);
            }
        }
        // store partials: part[(kh*3+g)*576 + b*18 + u], u pair as ull
        {
            #pragma unroll
            for (int b = 0; b < 2; b++) {
                float* pb = part + kh * 3 * 576 + (bg * 2 + b) * 18 + uh * 4;
                *(ull*)(pb)              = az[0][b];
                *(ull*)(pb + 2)          = az[1][b];
                *(ull*)(pb + 576)        = ar[0][b];
                *(ull*)(pb + 576 + 2)    = ar[1][b];
                *(ull*)(pb + 1152)       = ah[0][b];
                *(ull*)(pb + 1152 + 2)   = ah[1][b];
            }
        }
        __syncthreads();

        // combine: 2 outputs per thread (units cu2*2, cu2*2+1; batch cb)
        {
            float rz0 = brec[cu2 * 2],      rz1 = brec[cu2 * 2 + 1];
            float rr0 = brec[16 + cu2 * 2], rr1 = brec[16 + cu2 * 2 + 1];
            float rh0 = brec[32 + cu2 * 2], rh1 = brec[32 + cu2 * 2 + 1];
            #pragma unroll
            for (int q = 0; q < 4; q++) {
                const float* pq = part + q * 3 * 576 + cb * 18 + cu2 * 2;
                float2 v;
                v = upk2(*(const ull*)(pq));        rz0 += v.x; rz1 += v.y;
                v = upk2(*(const ull*)(pq + 576));  rr0 += v.x; rr1 += v.y;
                v = upk2(*(const ull*)(pq + 1152)); rh0 += v.x; rh1 += v.y;
            }
            const float h0 = hs[(u0 + cu2 * 2) * 32 + cb];
            const float h1 = hs[(u0 + cu2 * 2 + 1) * 32 + cb];

            const float z0 = 1.f / (1.f + expf(-(xg[0] + rz0)));
            const float z1 = 1.f / (1.f + expf(-(xg[1] + rz1)));
            const float r0 = 1.f / (1.f + expf(-(xg[2] + rr0)));
            const float r1 = 1.f / (1.f + expf(-(xg[3] + rr1)));
            const float c0 = tanhf(xg[4] + r0 * rh0);
            const float c1 = tanhf(xg[5] + r1 * rh1);
            const float hn0 = z0 * h0 + (1.f - z0) * c0;
            const float hn1 = z1 * h1 + (1.f - z1) * c1;

            float* hw = g_h + ((size_t)gid * 2 + (p ^ 1)) * UNITS * BPG;
            hw[(u0 + cu2 * 2) * 32 + cb]     = hn0;
            hw[(u0 + cu2 * 2 + 1) * 32 + cb] = hn1;

            float2 o2 = make_float2(hn0, hn1);
            *(float2*)(out + ((size_t)(B0 + cb) * TLEN + t) * 1024
                           + dir * 512 + u0 + cu2 * 2) = o2;
            if (s == TLEN - 1)
                *(float2*)(out + (size_t)BATCH * TLEN * 1024
                               + (size_t)(B0 + cb) * 1024
                               + dir * 512 + u0 + cu2 * 2) = o2;
        }
        gridbar_group(gid, 32);
    }
}

// ---------------- launch ----------------------------------------------------
extern "C" void kernel_launch(void* const* d_in, const int* in_sizes, int n_in,
                              void* d_out, int out_size)
{
    const int*   tokens = (const int*)  d_in[0];
    const float* emb    = (const float*)d_in[1];
    const float* W_f    = (const float*)d_in[2];
    const float* U_f    = (const float*)d_in[3];
    const float* b_f    = (const float*)d_in[4];
    const float* W_b    = (const float*)d_in[5];
    const float* U_b    = (const float*)d_in[6];
    const float* b_b    = (const float*)d_in[7];
    float* out = (float*)d_out;

    (void)in_sizes; (void)n_in; (void)out_size;

    dim3 g1(NC / 128, TLEN);
    embed_gemm<<<g1, 256>>>(tokens, emb, W_f, W_b, b_f, b_b);

    const size_t smem = (512 * 48 + 512 * 32 + 12 * 576) * sizeof(float); // 191488
    cudaFuncSetAttribute(gru_scan, cudaFuncAttributeMaxDynamicSharedMemorySize,
                         (int)smem);
    gru_scan<<<128, 256, smem>>>(U_f, U_b, b_f, b_b, out);
}

// round 6
// speedup vs baseline: 1.0857x; 1.0240x over previous
#include <cuda_runtime.h>
#include <math.h>

typedef unsigned long long ull;

#define EMBD   300
#define UNITS  512
#define BATCH  64
#define TLEN   512
#define NC     3072   // 2 * 3 * UNITS

// scan decomposition: 128 blocks = 2 dir x 2 batch-halves x 32 unit-slabs
#define UPB    16     // units per block
#define BPG    32     // batches per group

// ---------------- scratch (device globals; no allocations allowed) ----------
__device__ float g_xw[(size_t)TLEN * NC * BATCH];          // [t][c][b]
__device__ float g_h[2 * 2 * 2 * UNITS * BPG];             // [dir][bgrp][par][k][b32]

struct alignas(128) BarWord { unsigned int v; unsigned int pad[31]; };
__device__ BarWord g_cnt[4];
__device__ BarWord g_gen[4];

// ---------------- packed fp32x2 helpers -------------------------------------
__device__ __forceinline__ ull pk2(float lo, float hi) {
    ull r; asm("mov.b64 %0, {%1, %2};" : "=l"(r) : "f"(lo), "f"(hi)); return r;
}
__device__ __forceinline__ void fma2(ull& d, ull a, ull b) {
    asm("fma.rn.f32x2 %0, %1, %2, %0;" : "+l"(d) : "l"(a), "l"(b));
}
__device__ __forceinline__ float2 upk2(ull v) {
    float2 r; asm("mov.b64 {%0, %1}, %2;" : "=f"(r.x), "=f"(r.y) : "l"(v)); return r;
}

// ---------------- Kernel 1: embedding gather + input GEMM (64b x 128c) ------
__global__ __launch_bounds__(256) void embed_gemm(
    const int* __restrict__ tokens, const float* __restrict__ emb,
    const float* __restrict__ Wf, const float* __restrict__ Wb,
    const float* __restrict__ bf, const float* __restrict__ bb)
{
    __shared__ float As[16][64];    // [kk][b]
    __shared__ float Bs[16][128];   // [kk][c]
    __shared__ float Cs[128][65];   // [c][b]

    const int t   = blockIdx.y;
    const int c0  = blockIdx.x * 128;
    const int tid = threadIdx.x;
    const int tx  = tid & 15;
    const int ty  = tid >> 4;

    const int arow = tid >> 2;
    const int akk  = (tid & 3) * 4;
    const int tok  = tokens[(size_t)arow * TLEN + t];
    const float* aptr = emb + (size_t)tok * EMBD;

    const int brow = tid >> 4;
    const int bcol = (tid & 15) * 8;
    const bool fwd = (c0 < 1536);
    const float* W   = fwd ? Wf : Wb;
    const int    wc0 = fwd ? c0 : (c0 - 1536);

    ull acc2[4][4];
    #pragma unroll
    for (int i = 0; i < 4; i++)
        #pragma unroll
        for (int j = 0; j < 4; j++) acc2[i][j] = 0ull;

    for (int k0 = 0; k0 < EMBD; k0 += 16) {
        #pragma unroll
        for (int i = 0; i < 4; i++) {
            int k = k0 + akk + i;
            As[akk + i][arow] = (k < EMBD) ? aptr[k] : 0.f;
        }
        {
            int k = k0 + brow;
            if (k < EMBD) {
                const float* wp = W + (size_t)k * 1536 + wc0 + bcol;
                *(float4*)&Bs[brow][bcol]     = *(const float4*)wp;
                *(float4*)&Bs[brow][bcol + 4] = *(const float4*)(wp + 4);
            } else {
                *(float4*)&Bs[brow][bcol]     = make_float4(0, 0, 0, 0);
                *(float4*)&Bs[brow][bcol + 4] = make_float4(0, 0, 0, 0);
            }
        }
        __syncthreads();
        #pragma unroll
        for (int kk = 0; kk < 16; kk++) {
            const float4 a4 = *(const float4*)&As[kk][ty * 4];
            const float4 b0 = *(const float4*)&Bs[kk][tx * 8];
            const float4 b1 = *(const float4*)&Bs[kk][tx * 8 + 4];
            const ull bp[4] = {pk2(b0.x, b0.y), pk2(b0.z, b0.w),
                               pk2(b1.x, b1.y), pk2(b1.z, b1.w)};
            const float av[4] = {a4.x, a4.y, a4.z, a4.w};
            #pragma unroll
            for (int i = 0; i < 4; i++) {
                const ull ad = pk2(av[i], av[i]);
                #pragma unroll
                for (int j = 0; j < 4; j++) fma2(acc2[i][j], ad, bp[j]);
            }
        }
        __syncthreads();
    }

    const float* bias = fwd ? bf : bb;
    #pragma unroll
    for (int j = 0; j < 4; j++) {
        const float2 bv = make_float2(bias[wc0 + tx * 8 + j * 2],
                                      bias[wc0 + tx * 8 + j * 2 + 1]);
        #pragma unroll
        for (int i = 0; i < 4; i++) {
            const float2 v = upk2(acc2[i][j]);
            Cs[tx * 8 + j * 2][ty * 4 + i]     = v.x + bv.x;
            Cs[tx * 8 + j * 2 + 1][ty * 4 + i] = v.y + bv.y;
        }
    }
    __syncthreads();

    {   // coalesced store: g_xw[t][c0+cl][b]
        const int cl  = tid >> 1;
        const int bb0 = (tid & 1) * 32;
        float* dst = g_xw + ((size_t)t * NC + c0 + cl) * BATCH + bb0;
        #pragma unroll
        for (int j = 0; j < 32; j += 4) {
            float4 v = make_float4(Cs[cl][bb0 + j], Cs[cl][bb0 + j + 1],
                                   Cs[cl][bb0 + j + 2], Cs[cl][bb0 + j + 3]);
            *(float4*)(dst + j) = v;
        }
    }
}

// ---------------- per-group grid barrier (32 blocks) -------------------------
// padded counters (one 128B line each), tight L2 spin (no nanosleep)
__device__ __forceinline__ void gridbar_group(int gid, int nblk)
{
    __syncthreads();
    if (threadIdx.x == 0) {
        __threadfence();   // release (block's stores ordered via bar.sync)
        unsigned int gen0 = *(volatile unsigned int*)&g_gen[gid].v;
        unsigned int my   = atomicAdd(&g_cnt[gid].v, 1u);
        if (my == (unsigned)nblk - 1u) {
            *(volatile unsigned int*)&g_cnt[gid].v = 0u;
            __threadfence();
            atomicAdd(&g_gen[gid].v, 1u);
        } else {
            while (*(volatile unsigned int*)&g_gen[gid].v == gen0) { }
        }
        __threadfence();   // acquire
    }
    __syncthreads();
}

// ---------------- Kernel 2: persistent bidirectional GRU scan ---------------
// 512 threads/block; k split 8 ways. smem: Us[512][48] | hs[512][32] | part
__global__ __launch_bounds__(512, 1) void gru_scan(
    const float* __restrict__ Uf, const float* __restrict__ Ub,
    const float* __restrict__ bf, const float* __restrict__ bb,
    float* __restrict__ out)
{
    extern __shared__ float sm[];
    float* Us   = sm;                    // 512*48 = 24576 floats
    float* hs   = Us + 512 * 48;         // 512*32 = 16384
    float* part = hs + 512 * 32;         // 24*576 = 13824 (8 kh x 3 gates, row pad 18)
    __shared__ float brec[48];

    const int tid  = threadIdx.x;
    const int bid  = blockIdx.x;
    const int dir  = bid >> 6;
    const int bgrp = (bid >> 5) & 1;
    const int us   = bid & 31;
    const int gid  = dir * 2 + bgrp;
    const int u0   = us * UPB;
    const int B0   = bgrp * BPG;

    const float* U    = dir ? Ub : Uf;
    const float* brow = (dir ? bb : bf) + 1536;

    // U slab: Us[k][g*16+ui] = U[k][g*512 + u0 + ui]
    for (int l = tid; l < 512 * 48; l += 512) {
        int k = l / 48, j = l % 48;
        int g = j >> 4, ui = j & 15;
        Us[l] = U[(size_t)k * 1536 + g * 512 + u0 + ui];
    }
    if (tid < 48) brec[tid] = brow[(tid >> 4) * 512 + u0 + (tid & 15)];

    // zero h ping-pong: 131072 floats over 65536 threads -> 2 each
    {
        int l = (bid * 512 + tid) * 2;
        *(float2*)(g_h + l) = make_float2(0.f, 0.f);
    }
    gridbar_group(gid, 32);

    // matvec tiling: kh = k-eighth (64 k); uh = 4-unit group; bg = 2-batch group
    const int kh = tid >> 6;             // 0..7
    const int r  = tid & 63;
    const int uh = r & 3;                // 4 units: uh*4 .. uh*4+3
    const int bg = r >> 2;               // 0..15 -> batches 2bg, 2bg+1

    // combine mapping: one output per thread
    const int cb = tid & 31;             // batch lane
    const int cu = tid >> 5;             // local unit 0..15

    for (int s = 0; s < TLEN; s++) {
        const int p = s & 1;
        const int t = dir ? (TLEN - 1 - s) : s;

        // prefetch xw for combine (latency hidden under staging + matvec)
        float xg[3];
        {
            const float* xp = g_xw + ((size_t)t * NC + dir * 1536 + u0 + cu) * BATCH
                              + B0 + cb;
            #pragma unroll
            for (int g = 0; g < 3; g++)
                xg[g] = __ldg(xp + (size_t)g * 512 * BATCH);
        }

        // stage h_old slice [k][b32] (16K floats, 8 float4 per thread)
        {
            const float4* hg4 = (const float4*)(g_h +
                ((size_t)gid * 2 + p) * UNITS * BPG);
            float4* hs4 = (float4*)hs;
            #pragma unroll
            for (int l = tid; l < UNITS * BPG / 4; l += 512) hs4[l] = __ldg(hg4 + l);
        }
        __syncthreads();

        // rec partials: 4 units (2 pairs) x 2 batches x 3 gates over 64 k
        ull az[2][2], ar[2][2], ah[2][2];
        #pragma unroll
        for (int i = 0; i < 2; i++)
            #pragma unroll
            for (int j = 0; j < 2; j++) { az[i][j] = ar[i][j] = ah[i][j] = 0ull; }
        {
            const float* hp = hs + (size_t)kh * 64 * 32 + bg * 2;
            const float* up = Us + (size_t)kh * 64 * 48 + uh * 4;
            #pragma unroll 4
            for (int k = 0; k < 64; k++) {
                const float2 h2 = *(const float2*)(hp + k * 32);
                const ull hd0 = pk2(h2.x, h2.x);
                const ull hd1 = pk2(h2.y, h2.y);
                const float4 z4 = *(const float4*)(up + k * 48);
                const float4 r4 = *(const float4*)(up + k * 48 + 16);
                const float4 q4 = *(const float4*)(up + k * 48 + 32);
                const ull z0 = pk2(z4.x, z4.y), z1 = pk2(z4.z, z4.w);
                const ull r0 = pk2(r4.x, r4.y), r1 = pk2(r4.z, r4.w);
                const ull q0 = pk2(q4.x, q4.y), q1 = pk2(q4.z, q4.w);
                fma2(az[0][0], z0, hd0); fma2(az[1][0], z1, hd0);
                fma2(az[0][1], z0, hd1); fma2(az[1][1], z1, hd1);
                fma2(ar[0][0], r0, hd0); fma2(ar[1][0], r1, hd0);
                fma2(ar[0][1], r0, hd1); fma2(ar[1][1], r1, hd1);
                fma2(ah[0][0], q0, hd0); fma2(ah[1][0], q1, hd0);
                fma2(ah[0][1], q0, hd1); fma2(ah[1][1], q1, hd1);
            }
        }
        // store partials: part[(kh*3+g)*576 + b*18 + u]
        {
            #pragma unroll
            for (int b = 0; b < 2; b++) {
                float* pb = part + kh * 3 * 576 + (bg * 2 + b) * 18 + uh * 4;
                *(ull*)(pb)            = az[0][b];
                *(ull*)(pb + 2)        = az[1][b];
                *(ull*)(pb + 576)      = ar[0][b];
                *(ull*)(pb + 576 + 2)  = ar[1][b];
                *(ull*)(pb + 1152)     = ah[0][b];
                *(ull*)(pb + 1152 + 2) = ah[1][b];
            }
        }
        __syncthreads();

        // combine: one h_new per thread (unit cu, batch cb)
        {
            float rz = brec[cu], rr = brec[16 + cu], rh = brec[32 + cu];
            #pragma unroll
            for (int q = 0; q < 8; q++) {
                const float* pq = part + q * 3 * 576 + cb * 18 + cu;
                rz += pq[0];
                rr += pq[576];
                rh += pq[1152];
            }
            const float hold = hs[(u0 + cu) * 32 + cb];

            const float z  = 1.f / (1.f + expf(-(xg[0] + rz)));
            const float rg = 1.f / (1.f + expf(-(xg[1] + rr)));
            const float hh = tanhf(xg[2] + rg * rh);
            const float hn = z * hold + (1.f - z) * hh;

            float* hw = g_h + ((size_t)gid * 2 + (p ^ 1)) * UNITS * BPG;
            hw[(u0 + cu) * 32 + cb] = hn;

            out[((size_t)(B0 + cb) * TLEN + t) * 1024 + dir * 512 + u0 + cu] = hn;
            if (s == TLEN - 1)
                out[(size_t)BATCH * TLEN * 1024 + (size_t)(B0 + cb) * 1024
                    + dir * 512 + u0 + cu] = hn;
        }
        gridbar_group(gid, 32);
    }
}

// ---------------- launch ----------------------------------------------------
extern "C" void kernel_launch(void* const* d_in, const int* in_sizes, int n_in,
                              void* d_out, int out_size)
{
    const int*   tokens = (const int*)  d_in[0];
    const float* emb    = (const float*)d_in[1];
    const float* W_f    = (const float*)d_in[2];
    const float* U_f    = (const float*)d_in[3];
    const float* b_f    = (const float*)d_in[4];
    const float* W_b    = (const float*)d_in[5];
    const float* U_b    = (const float*)d_in[6];
    const float* b_b    = (const float*)d_in[7];
    float* out = (float*)d_out;

    (void)in_sizes; (void)n_in; (void)out_size;

    dim3 g1(NC / 128, TLEN);
    embed_gemm<<<g1, 256>>>(tokens, emb, W_f, W_b, b_f, b_b);

    const size_t smem = (512 * 48 + 512 * 32 + 24 * 576) * sizeof(float); // 219136
    cudaFuncSetAttribute(gru_scan, cudaFuncAttributeMaxDynamicSharedMemorySize,
                         (int)smem);
    gru_scan<<<128, 512, smem>>>(U_f, U_b, b_f, b_b, out);
}

// round 7
// speedup vs baseline: 1.2425x; 1.1445x over previous
#include <cuda_runtime.h>
#include <math.h>

typedef unsigned long long ull;

#define EMBD   300
#define UNITS  512
#define BATCH  64
#define TLEN   512
#define NC     3072   // 2 * 3 * UNITS

// scan decomposition: 128 blocks = 2 dir x 2 batch-halves x 32 unit-slabs
#define UPB    16     // units per block
#define BPG    32     // batches per group

// ---------------- scratch (device globals; no allocations allowed) ----------
__device__ float g_xw[(size_t)TLEN * NC * BATCH];          // [t][c][b]
__device__ float g_h[2 * 2 * 2 * UNITS * BPG];             // [dir][bgrp][par][k][b32]

struct alignas(128) BarWord { unsigned int v; unsigned int pad[31]; };
__device__ BarWord g_cnt[4];
__device__ BarWord g_gen[4];

// ---------------- packed fp32x2 helpers -------------------------------------
__device__ __forceinline__ ull pk2(float lo, float hi) {
    ull r; asm("mov.b64 %0, {%1, %2};" : "=l"(r) : "f"(lo), "f"(hi)); return r;
}
__device__ __forceinline__ void fma2(ull& d, ull a, ull b) {
    asm("fma.rn.f32x2 %0, %1, %2, %0;" : "+l"(d) : "l"(a), "l"(b));
}
__device__ __forceinline__ float2 upk2(ull v) {
    float2 r; asm("mov.b64 {%0, %1}, %2;" : "=f"(r.x), "=f"(r.y) : "l"(v)); return r;
}

// ---------------- Kernel 1: embedding gather + input GEMM (64b x 128c) ------
__global__ __launch_bounds__(256) void embed_gemm(
    const int* __restrict__ tokens, const float* __restrict__ emb,
    const float* __restrict__ Wf, const float* __restrict__ Wb,
    const float* __restrict__ bf, const float* __restrict__ bb)
{
    __shared__ float As[16][64];    // [kk][b]
    __shared__ float Bs[16][128];   // [kk][c]
    __shared__ float Cs[128][65];   // [c][b]

    const int t   = blockIdx.y;
    const int c0  = blockIdx.x * 128;
    const int tid = threadIdx.x;
    const int tx  = tid & 15;
    const int ty  = tid >> 4;

    const int arow = tid >> 2;
    const int akk  = (tid & 3) * 4;
    const int tok  = tokens[(size_t)arow * TLEN + t];
    const float* aptr = emb + (size_t)tok * EMBD;

    const int brow = tid >> 4;
    const int bcol = (tid & 15) * 8;
    const bool fwd = (c0 < 1536);
    const float* W   = fwd ? Wf : Wb;
    const int    wc0 = fwd ? c0 : (c0 - 1536);

    ull acc2[4][4];
    #pragma unroll
    for (int i = 0; i < 4; i++)
        #pragma unroll
        for (int j = 0; j < 4; j++) acc2[i][j] = 0ull;

    for (int k0 = 0; k0 < EMBD; k0 += 16) {
        #pragma unroll
        for (int i = 0; i < 4; i++) {
            int k = k0 + akk + i;
            As[akk + i][arow] = (k < EMBD) ? aptr[k] : 0.f;
        }
        {
            int k = k0 + brow;
            if (k < EMBD) {
                const float* wp = W + (size_t)k * 1536 + wc0 + bcol;
                *(float4*)&Bs[brow][bcol]     = *(const float4*)wp;
                *(float4*)&Bs[brow][bcol + 4] = *(const float4*)(wp + 4);
            } else {
                *(float4*)&Bs[brow][bcol]     = make_float4(0, 0, 0, 0);
                *(float4*)&Bs[brow][bcol + 4] = make_float4(0, 0, 0, 0);
            }
        }
        __syncthreads();
        #pragma unroll
        for (int kk = 0; kk < 16; kk++) {
            const float4 a4 = *(const float4*)&As[kk][ty * 4];
            const float4 b0 = *(const float4*)&Bs[kk][tx * 8];
            const float4 b1 = *(const float4*)&Bs[kk][tx * 8 + 4];
            const ull bp[4] = {pk2(b0.x, b0.y), pk2(b0.z, b0.w),
                               pk2(b1.x, b1.y), pk2(b1.z, b1.w)};
            const float av[4] = {a4.x, a4.y, a4.z, a4.w};
            #pragma unroll
            for (int i = 0; i < 4; i++) {
                const ull ad = pk2(av[i], av[i]);
                #pragma unroll
                for (int j = 0; j < 4; j++) fma2(acc2[i][j], ad, bp[j]);
            }
        }
        __syncthreads();
    }

    const float* bias = fwd ? bf : bb;
    #pragma unroll
    for (int j = 0; j < 4; j++) {
        const float2 bv = make_float2(bias[wc0 + tx * 8 + j * 2],
                                      bias[wc0 + tx * 8 + j * 2 + 1]);
        #pragma unroll
        for (int i = 0; i < 4; i++) {
            const float2 v = upk2(acc2[i][j]);
            Cs[tx * 8 + j * 2][ty * 4 + i]     = v.x + bv.x;
            Cs[tx * 8 + j * 2 + 1][ty * 4 + i] = v.y + bv.y;
        }
    }
    __syncthreads();

    {   // coalesced store: g_xw[t][c0+cl][b]
        const int cl  = tid >> 1;
        const int bb0 = (tid & 1) * 32;
        float* dst = g_xw + ((size_t)t * NC + c0 + cl) * BATCH + bb0;
        #pragma unroll
        for (int j = 0; j < 32; j += 4) {
            float4 v = make_float4(Cs[cl][bb0 + j], Cs[cl][bb0 + j + 1],
                                   Cs[cl][bb0 + j + 2], Cs[cl][bb0 + j + 3]);
            *(float4*)(dst + j) = v;
        }
    }
}

// ---------------- split per-group barrier (32 blocks) ------------------------
__device__ __forceinline__ void bar_arrive(int gid, int nblk)
{
    __syncthreads();                      // all h stores issued
    if (threadIdx.x == 0) {
        __threadfence();                  // release
        unsigned int my = atomicAdd(&g_cnt[gid].v, 1u);
        if (my == (unsigned)nblk - 1u) {
            *(volatile unsigned int*)&g_cnt[gid].v = 0u;
            __threadfence();
            atomicAdd(&g_gen[gid].v, 1u);
        }
    }
}
__device__ __forceinline__ void bar_wait(int gid, unsigned int gen0)
{
    if (threadIdx.x == 0) {
        while (*(volatile unsigned int*)&g_gen[gid].v == gen0) { }
        __threadfence();                  // acquire
    }
    __syncthreads();
}

// ---------------- Kernel 2: persistent bidirectional GRU scan ---------------
// 256 threads/block. matvec tile: 4 units x 4 batches per thread, k split 8.
// smem: Us[512][48] | hs[512][32] | part[8][3][32][18]
__global__ __launch_bounds__(256, 1) void gru_scan(
    const float* __restrict__ Uf, const float* __restrict__ Ub,
    const float* __restrict__ bf, const float* __restrict__ bb,
    float* __restrict__ out)
{
    extern __shared__ float sm[];
    float* Us   = sm;                    // 24576 floats (96KB)
    float* hs   = Us + 512 * 48;         // 16384 floats (64KB)
    float* part = hs + 512 * 32;         // 8*3*576 = 13824 floats (54KB)
    __shared__ float brec[48];

    const int tid  = threadIdx.x;
    const int bid  = blockIdx.x;
    const int dir  = bid >> 6;
    const int bgrp = (bid >> 5) & 1;
    const int us   = bid & 31;
    const int gid  = dir * 2 + bgrp;
    const int u0   = us * UPB;
    const int B0   = bgrp * BPG;

    const float* U    = dir ? Ub : Uf;
    const float* brow = (dir ? bb : bf) + 1536;

    // U slab: Us[k][g*16+ui] = U[k][g*512 + u0 + ui]
    for (int l = tid; l < 512 * 48; l += 256) {
        int k = l / 48, j = l % 48;
        int g = j >> 4, ui = j & 15;
        Us[l] = U[(size_t)k * 1536 + g * 512 + u0 + ui];
    }
    if (tid < 48) brec[tid] = brow[(tid >> 4) * 512 + u0 + (tid & 15)];

    // zero h ping-pong: 131072 floats over 32768 threads -> 4 each
    {
        int l = (bid * 256 + tid) * 4;
        *(float4*)(g_h + l) = make_float4(0.f, 0.f, 0.f, 0.f);
    }
    unsigned int gen = *(volatile unsigned int*)&g_gen[gid].v;
    bar_arrive(gid, 32);
    bar_wait(gid, gen);
    gen++;

    // matvec tiling: warp = kh (8 warps x 64 k); lanes: uh(4) x bg(8)
    const int kh = tid >> 5;
    const int uh = tid & 3;              // units uh*4..uh*4+3
    const int bg = (tid >> 2) & 7;       // batches bg*4..bg*4+3

    // combine mapping: 2 outputs per thread; lanes unit-major for coalesced out
    const int cu2 = tid & 7;             // unit pair: cu2*2, cu2*2+1
    const int cb  = tid >> 3;            // batch 0..31

    // xw prefetch for step 0
    float xg[6];
    {
        const int t0 = dir ? (TLEN - 1) : 0;
        const float* xp = g_xw + ((size_t)t0 * NC + dir * 1536 + u0 + cu2 * 2) * BATCH
                          + B0 + cb;
        #pragma unroll
        for (int g = 0; g < 3; g++) {
            xg[g * 2]     = __ldg(xp + (size_t)g * 512 * BATCH);
            xg[g * 2 + 1] = __ldg(xp + ((size_t)g * 512 + 1) * BATCH);
        }
    }

    for (int s = 0; s < TLEN; s++) {
        const int p = s & 1;
        const int t = dir ? (TLEN - 1 - s) : s;

        // stage h_old slice [k][b32]: 4096 float4, 16 per thread
        {
            const float4* hg4 = (const float4*)(g_h +
                ((size_t)gid * 2 + p) * UNITS * BPG);
            float4* hs4 = (float4*)hs;
            #pragma unroll
            for (int l = tid; l < UNITS * BPG / 4; l += 256) hs4[l] = __ldg(hg4 + l);
        }
        __syncthreads();

        // matvec: 4 units x 4 batches x 3 gates over 64 k (24 fma2 per k)
        ull az[2][4], ar[2][4], ah[2][4];
        #pragma unroll
        for (int i = 0; i < 2; i++)
            #pragma unroll
            for (int j = 0; j < 4; j++) { az[i][j] = ar[i][j] = ah[i][j] = 0ull; }
        {
            const float* hp = hs + (size_t)kh * 64 * 32 + bg * 4;
            const float* up = Us + (size_t)kh * 64 * 48 + uh * 4;
            #pragma unroll 2
            for (int k = 0; k < 64; k++) {
                const float4 h4 = *(const float4*)(hp + k * 32);
                const float4 z4 = *(const float4*)(up + k * 48);
                const float4 r4 = *(const float4*)(up + k * 48 + 16);
                const float4 q4 = *(const float4*)(up + k * 48 + 32);
                const ull hd[4] = {pk2(h4.x, h4.x), pk2(h4.y, h4.y),
                                   pk2(h4.z, h4.z), pk2(h4.w, h4.w)};
                const ull z0 = pk2(z4.x, z4.y), z1 = pk2(z4.z, z4.w);
                const ull r0 = pk2(r4.x, r4.y), r1 = pk2(r4.z, r4.w);
                const ull q0 = pk2(q4.x, q4.y), q1 = pk2(q4.z, q4.w);
                #pragma unroll
                for (int b = 0; b < 4; b++) {
                    fma2(az[0][b], z0, hd[b]); fma2(az[1][b], z1, hd[b]);
                    fma2(ar[0][b], r0, hd[b]); fma2(ar[1][b], r1, hd[b]);
                    fma2(ah[0][b], q0, hd[b]); fma2(ah[1][b], q1, hd[b]);
                }
            }
        }
        // part[(kh*3+g)*576 + b*18 + u]
        {
            #pragma unroll
            for (int b = 0; b < 4; b++) {
                float* pb = part + kh * 3 * 576 + (bg * 4 + b) * 18 + uh * 4;
                *(ull*)(pb)            = az[0][b];
                *(ull*)(pb + 2)        = az[1][b];
                *(ull*)(pb + 576)      = ar[0][b];
                *(ull*)(pb + 576 + 2)  = ar[1][b];
                *(ull*)(pb + 1152)     = ah[0][b];
                *(ull*)(pb + 1152 + 2) = ah[1][b];
            }
        }
        __syncthreads();

        // combine: units cu2*2, cu2*2+1; batch cb
        float hn0, hn1;
        {
            float rz0 = brec[cu2 * 2],      rz1 = brec[cu2 * 2 + 1];
            float rr0 = brec[16 + cu2 * 2], rr1 = brec[16 + cu2 * 2 + 1];
            float rh0 = brec[32 + cu2 * 2], rh1 = brec[32 + cu2 * 2 + 1];
            #pragma unroll
            for (int q = 0; q < 8; q++) {
                const float* pq = part + q * 3 * 576 + cb * 18 + cu2 * 2;
                float2 v;
                v = upk2(*(const ull*)(pq));        rz0 += v.x; rz1 += v.y;
                v = upk2(*(const ull*)(pq + 576));  rr0 += v.x; rr1 += v.y;
                v = upk2(*(const ull*)(pq + 1152)); rh0 += v.x; rh1 += v.y;
            }
            const float h0 = hs[(u0 + cu2 * 2) * 32 + cb];
            const float h1 = hs[(u0 + cu2 * 2 + 1) * 32 + cb];

            const float z0 = 1.f / (1.f + expf(-(xg[0] + rz0)));
            const float z1 = 1.f / (1.f + expf(-(xg[1] + rz1)));
            const float r0 = 1.f / (1.f + expf(-(xg[2] + rr0)));
            const float r1 = 1.f / (1.f + expf(-(xg[3] + rr1)));
            const float c0 = tanhf(xg[4] + r0 * rh0);
            const float c1 = tanhf(xg[5] + r1 * rh1);
            hn0 = z0 * h0 + (1.f - z0) * c0;
            hn1 = z1 * h1 + (1.f - z1) * c1;

            float* hw = g_h + ((size_t)gid * 2 + (p ^ 1)) * UNITS * BPG;
            hw[(u0 + cu2 * 2) * 32 + cb]     = hn0;
            hw[(u0 + cu2 * 2 + 1) * 32 + cb] = hn1;
        }
        bar_arrive(gid, 32);   // h published

        // ---- latency cover between arrive and wait ----
        {
            float2 o2 = make_float2(hn0, hn1);
            *(float2*)(out + ((size_t)(B0 + cb) * TLEN + t) * 1024
                           + dir * 512 + u0 + cu2 * 2) = o2;
            if (s == TLEN - 1)
                *(float2*)(out + (size_t)BATCH * TLEN * 1024
                               + (size_t)(B0 + cb) * 1024
                               + dir * 512 + u0 + cu2 * 2) = o2;
        }
        if (s + 1 < TLEN) {   // prefetch xw for next step
            const int tn = dir ? (TLEN - 2 - s) : (s + 1);
            const float* xp = g_xw + ((size_t)tn * NC + dir * 1536 + u0 + cu2 * 2) * BATCH
                              + B0 + cb;
            #pragma unroll
            for (int g = 0; g < 3; g++) {
                xg[g * 2]     = __ldg(xp + (size_t)g * 512 * BATCH);
                xg[g * 2 + 1] = __ldg(xp + ((size_t)g * 512 + 1) * BATCH);
            }
        }
        bar_wait(gid, gen);
        gen++;
    }
}

// ---------------- launch ----------------------------------------------------
extern "C" void kernel_launch(void* const* d_in, const int* in_sizes, int n_in,
                              void* d_out, int out_size)
{
    const int*   tokens = (const int*)  d_in[0];
    const float* emb    = (const float*)d_in[1];
    const float* W_f    = (const float*)d_in[2];
    const float* U_f    = (const float*)d_in[3];
    const float* b_f    = (const float*)d_in[4];
    const float* W_b    = (const float*)d_in[5];
    const float* U_b    = (const float*)d_in[6];
    const float* b_b    = (const float*)d_in[7];
    float* out = (float*)d_out;

    (void)in_sizes; (void)n_in; (void)out_size;

    dim3 g1(NC / 128, TLEN);
    embed_gemm<<<g1, 256>>>(tokens, emb, W_f, W_b, b_f, b_b);

    const size_t smem = (512 * 48 + 512 * 32 + 24 * 576) * sizeof(float); // 219136
    cudaFuncSetAttribute(gru_scan, cudaFuncAttributeMaxDynamicSharedMemorySize,
                         (int)smem);
    gru_scan<<<128, 256, smem>>>(U_f, U_b, b_f, b_b, out);
}